// round 15
// baseline (speedup 1.0000x reference)
#include <cuda_runtime.h>
#include <cstdint>

// ---------------------------------------------------------------------------
// Problem constants
// ---------------------------------------------------------------------------
#define BS 4
#define LQ 1024
#define EMBED 256
#define NH 8
#define NL 4
#define NP 16
#define HD 32
#define LEN_V 5440
#define MQ (BS * LQ)        // 4096
#define MV (BS * LEN_V)     // 21760

#define OUT_ELEMS   (BS * LQ * EMBED)
#define LOC_OFFSET  (OUT_ELEMS)
#define LOC_ELEMS   (BS * LQ * NH * NL * NP * 2)
#define ATTN_OFFSET (LOC_OFFSET + LOC_ELEMS)

__constant__ int   c_H[NL]      = {64, 32, 16, 8};
__constant__ int   c_W[NL]      = {64, 32, 16, 8};
__constant__ int   c_start[NL]  = {0, 4096, 5120, 5376};
__constant__ float c_invW[NL]   = {1.0f/64, 1.0f/32, 1.0f/16, 1.0f/8};
__constant__ float c_invH[NL]   = {1.0f/64, 1.0f/32, 1.0f/16, 1.0f/8};

__device__ float  g_v[MV * EMBED];                    // projected value ~22.3 MB
__device__ float  g_midT[EMBED * MQ];                 // pre-W_out, k-major  4 MB
__device__ float4 g_meta[MQ * NH * 32 * 4];           // gather meta     ~67 MB
__device__ float  g_vT[EMBED * MV];                   // value transposed 22.3 MB
__device__ float  g_qT[EMBED * MQ];                   // query transposed  4 MB

// ---------------------------------------------------------------------------
// Packed f32x2 + cp.async helpers
// ---------------------------------------------------------------------------
__device__ __forceinline__ uint64_t pack2(float x, float y) {
    uint64_t r;
    asm("mov.b64 %0, {%1, %2};" : "=l"(r) : "f"(x), "f"(y));
    return r;
}
__device__ __forceinline__ void unpack2(uint64_t v, float& x, float& y) {
    asm("mov.b64 {%0, %1}, %2;" : "=f"(x), "=f"(y) : "l"(v));
}
__device__ __forceinline__ void ffma2(uint64_t& d, uint64_t a, uint64_t b) {
    asm("fma.rn.f32x2 %0, %1, %2, %0;" : "+l"(d) : "l"(a), "l"(b));
}
__device__ __forceinline__ void cp16(void* s, const void* g) {
    uint32_t sa = (uint32_t)__cvta_generic_to_shared(s);
    asm volatile("cp.async.ca.shared.global [%0], [%1], 16;" :: "r"(sa), "l"(g));
}
#define CP_COMMIT() asm volatile("cp.async.commit_group;" ::: "memory")
#define CP_WAIT(N)  asm volatile("cp.async.wait_group %0;" :: "n"(N) : "memory")

// ---------------------------------------------------------------------------
// Transpose kernel: value[MV,256] -> vT[256,MV], query[MQ,256] -> qT[256,MQ]
// ---------------------------------------------------------------------------
#define VT_TILES ((MV / 32) * (EMBED / 32))   // 5440
#define QT_TILES ((MQ / 32) * (EMBED / 32))   // 1024

__global__ __launch_bounds__(256) void transpose_kernel(
    const float* __restrict__ value, const float* __restrict__ query,
    float* __restrict__ vT, float* __restrict__ qT)
{
    __shared__ float tile[32][33];
    int t = blockIdx.x;
    const float* src; float* dst; int Mr, tm, tk;
    if (t < VT_TILES) { src = value; dst = vT; Mr = MV; tm = t >> 3; tk = t & 7; }
    else { t -= VT_TILES; src = query; dst = qT; Mr = MQ; tm = t >> 3; tk = t & 7; }

    const int r  = threadIdx.x >> 3;
    const int c4 = threadIdx.x & 7;

    float4 v = *(const float4*)(src + (size_t)(tm * 32 + r) * EMBED + tk * 32 + c4 * 4);
    tile[r][c4 * 4 + 0] = v.x;
    tile[r][c4 * 4 + 1] = v.y;
    tile[r][c4 * 4 + 2] = v.z;
    tile[r][c4 * 4 + 3] = v.w;
    __syncthreads();

    float4 w;
    w.x = tile[c4 * 4 + 0][r];
    w.y = tile[c4 * 4 + 1][r];
    w.z = tile[c4 * 4 + 2][r];
    w.w = tile[c4 * 4 + 3][r];
    *(float4*)(dst + (size_t)(tk * 32 + r) * Mr + tm * 32 + c4 * 4) = w;
}

// ---------------------------------------------------------------------------
// MEGA GEMM with cp.async 4-stage pipeline.
// Tiling: 128x128xBK16, 256 thr, microtile 8x8 (warp 4m x 2n).
// ---------------------------------------------------------------------------
#define TBK  16
#define SAm  128
#define SBm  192
#define STGA (TBK * SAm)               // 2048 floats
#define STGB (TBK * SBm)               // 3072 floats
#define MEGA_SMEM (4 * (STGA + STGB) * 4)   // 81920 B
#define KK   256

#define G3_CTAS 340
#define G1_CTAS 256
#define G2_CTAS 128
#define MEGA_CTAS (G3_CTAS + G1_CTAS + G2_CTAS)

__global__ __launch_bounds__(256, 2) void mega_gemm(
    const float* __restrict__ vT, const float* __restrict__ qT,
    const float* __restrict__ W_val, const float* __restrict__ b_val,
    const float* __restrict__ W_off, const float* __restrict__ b_off,
    const float* __restrict__ W_attn, const float* __restrict__ b_attn,
    const float* __restrict__ refp,
    float* __restrict__ gv, float* __restrict__ loc,
    float* __restrict__ attn_out, float4* __restrict__ meta)
{
    extern __shared__ __align__(16) float smem[];
    float* As = smem;                  // 4 stages x STGA
    float* Bs = smem + 4 * STGA;       // 4 stages x STGB

    const int cta = blockIdx.x;
    const float *AT, *B, *bias;
    float* C;
    int N, mode, gx, gy, Mlen;
    if (cta < G3_CTAS) {
        AT = vT; Mlen = MV; B = W_val; bias = b_val; C = gv;
        N = 256; mode = 0; gx = cta & 1; gy = cta >> 1;
    } else if (cta < G3_CTAS + G1_CTAS) {
        int l = cta - G3_CTAS;
        AT = qT; Mlen = MQ; B = W_off; bias = b_off; C = loc;
        N = 1024; mode = 1; gx = l & 7; gy = l >> 3;
    } else {
        int l = cta - (G3_CTAS + G1_CTAS);
        AT = qT; Mlen = MQ; B = W_attn; bias = b_attn; C = attn_out;
        N = 512; mode = 2; gx = l & 3; gy = l >> 2;
    }
    const int m0 = gy * 128;
    const int n0 = gx * 128;

    const int tid  = threadIdx.x;
    const int lane = tid & 31;
    const int wid  = tid >> 5;
    const int wm   = wid & 3;
    const int wn   = wid >> 2;
    const int lm   = lane & 3;
    const int ln   = lane >> 2;

    const int aofs = wm * 32 + lm * 8;
    const int bofs = (wn * 8 + ln) * 12;
    const int mb   = wm * 32 + lm * 8;
    const int nb   = wn * 64 + ln * 8;

    auto stage = [&](int sg, int kt) {
        const int k0 = kt * TBK;
#pragma unroll
        for (int r2 = 0; r2 < 2; r2++) {
            int i = tid + r2 * 256;
            int k = i >> 5, m4 = i & 31;
            cp16(As + sg * STGA + k * SAm + m4 * 4,
                 AT + (size_t)(k0 + k) * Mlen + m0 + m4 * 4);
        }
#pragma unroll
        for (int r2 = 0; r2 < 2; r2++) {
            int i = tid + r2 * 256;
            int kk = i >> 5, n4 = i & 31;
            cp16(Bs + sg * STGB + kk * SBm + (n4 >> 1) * 12 + (n4 & 1) * 4,
                 B + (size_t)(k0 + kk) * N + n0 + n4 * 4);
        }
    };

    stage(0, 0); CP_COMMIT();
    stage(1, 1); CP_COMMIT();
    stage(2, 2); CP_COMMIT();

    uint64_t acc[8][4];
#pragma unroll
    for (int i = 0; i < 8; i++)
#pragma unroll
        for (int j = 0; j < 4; j++) acc[i][j] = 0ull;

    const int KT = KK / TBK;   // 16
    int cur = 0;

#pragma unroll 1
    for (int kt = 0; kt < KT; kt++) {
        if (kt <= KT - 3)      { CP_WAIT(2); }
        else if (kt == KT - 2) { CP_WAIT(1); }
        else                   { CP_WAIT(0); }
        __syncthreads();
        if (kt + 3 < KT) {
            stage((kt + 3) & 3, kt + 3);
            CP_COMMIT();
        }

#pragma unroll
        for (int k = 0; k < TBK; k++) {
            const float* ap = As + cur * STGA + k * SAm + aofs;
            float4 a0 = *(const float4*)(ap);
            float4 a1 = *(const float4*)(ap + 4);
            const uint64_t* bp = (const uint64_t*)(Bs + cur * STGB + k * SBm + bofs);
            uint64_t bd[4];
            bd[0] = bp[0]; bd[1] = bp[1]; bd[2] = bp[2]; bd[3] = bp[3];
            uint64_t ad[8];
            ad[0] = pack2(a0.x, a0.x);
            ad[1] = pack2(a0.y, a0.y);
            ad[2] = pack2(a0.z, a0.z);
            ad[3] = pack2(a0.w, a0.w);
            ad[4] = pack2(a1.x, a1.x);
            ad[5] = pack2(a1.y, a1.y);
            ad[6] = pack2(a1.z, a1.z);
            ad[7] = pack2(a1.w, a1.w);
#pragma unroll
            for (int i = 0; i < 8; i++)
#pragma unroll
                for (int j = 0; j < 4; j++)
                    ffma2(acc[i][j], ad[i], bd[j]);
        }

        cur = (cur + 1) & 3;
    }

    float bn[8];
#pragma unroll
    for (int j = 0; j < 8; j++) bn[j] = __ldg(&bias[n0 + nb + j]);

    float o[8][8];
#pragma unroll
    for (int i = 0; i < 8; i++) {
#pragma unroll
        for (int j = 0; j < 4; j++)
            unpack2(acc[i][j], o[i][2 * j], o[i][2 * j + 1]);
#pragma unroll
        for (int j = 0; j < 8; j++) o[i][j] += bn[j];
    }

    if (mode == 0) {
#pragma unroll
        for (int i = 0; i < 8; i++) {
            float* crow = C + (size_t)(m0 + mb + i) * N + n0 + nb;
            *(float4*)(crow)     = make_float4(o[i][0], o[i][1], o[i][2], o[i][3]);
            *(float4*)(crow + 4) = make_float4(o[i][4], o[i][5], o[i][6], o[i][7]);
        }
    } else if (mode == 1) {
        // ---- sampling-location transform + gather-meta (pair-corner layout) ----
        __syncthreads();
        float* rps = As;
        {
            int row = tid >> 1, half = tid & 1;
            *(float4*)(rps + row * 8 + half * 4) =
                *(const float4*)(refp + (size_t)(m0 + row) * 8 + half * 4);
        }
        __syncthreads();

        const int h = gx;
        const int lvl = wn * 2 + (ln >> 2);
        const int W = c_W[lvl], H = c_H[lvl];
        const float fW = (float)W, fH = (float)H;
        const float invW = c_invW[lvl], invH = c_invH[lvl];
        const int cstE = c_start[lvl] * EMBED;
        const int pbase = (ln & 3) * 4;

#pragma unroll
        for (int i = 0; i < 8; i++) {
            const int bq = m0 + mb + i;
            const float* rp = rps + (mb + i) * 8;
            float rx0 = rp[0], rx1 = rp[1], rx2 = rp[2], rx3 = rp[3];
            float ry0 = rp[4], ry1 = rp[5], ry2 = rp[6], ry3 = rp[7];
            float res[8];
#pragma unroll
            for (int j = 0; j < 8; j++) {
                int p = pbase + (j >> 1);
                int c = j & 1;
                float lam = (float)p * (1.0f / 15.0f);
                float pnt = c ? (((ry0 * lam + ry1) * lam + ry2) * lam + ry3)
                              : (((rx0 * lam + rx1) * lam + rx2) * lam + rx3);
                float inv = c ? invH : invW;
                res[j] = pnt + o[i][j] * inv;
            }
            float* crow = C + (size_t)bq * N + n0 + nb;
            *(float4*)(crow)     = make_float4(res[0], res[1], res[2], res[3]);
            *(float4*)(crow + 4) = make_float4(res[4], res[5], res[6], res[7]);

            float4 cm[4];
            float4* mb4 = meta + ((size_t)(bq * NH + h) * 32 + lvl * 8 + (pbase >> 1)) * 4;
#pragma unroll
            for (int t = 0; t < 4; t++) {
                float x = res[2 * t]     * fW - 0.5f;
                float y = res[2 * t + 1] * fH - 0.5f;
                float x0f = floorf(x);
                float y0f = floorf(y);
                float wx = x - x0f;
                float wy = y - y0f;
                int x0 = (int)x0f, y0 = (int)y0f;
                int x1 = x0 + 1,   y1 = y0 + 1;

                bool vx0 = (x0 >= 0) & (x0 < W);
                bool vx1 = (x1 >= 0) & (x1 < W);
                bool vy0 = (y0 >= 0) & (y0 < H);
                bool vy1 = (y1 >= 0) & (y1 < H);

                float w00 = (vx0 & vy0) ? (1.0f - wx) * (1.0f - wy) : 0.0f;
                float w10 = (vx1 & vy0) ? wx * (1.0f - wy)          : 0.0f;
                float w01 = (vx0 & vy1) ? (1.0f - wx) * wy          : 0.0f;
                float w11 = (vx1 & vy1) ? wx * wy                   : 0.0f;

                int cx0 = min(max(x0, 0), W - 1);
                int cx1 = min(max(x1, 0), W - 1);
                int cy0 = min(max(y0, 0), H - 1);
                int cy1 = min(max(y1, 0), H - 1);

                float i00 = __int_as_float(cstE + (cy0 * W + cx0) * EMBED);
                float i10 = __int_as_float(cstE + (cy0 * W + cx1) * EMBED);
                float i01 = __int_as_float(cstE + (cy1 * W + cx0) * EMBED);
                float i11 = __int_as_float(cstE + (cy1 * W + cx1) * EMBED);

                if ((t & 1) == 0) {
                    cm[0].x = i00; cm[0].y = w00;
                    cm[1].x = i10; cm[1].y = w10;
                    cm[2].x = i01; cm[2].y = w01;
                    cm[3].x = i11; cm[3].y = w11;
                } else {
                    cm[0].z = i00; cm[0].w = w00;
                    cm[1].z = i10; cm[1].w = w10;
                    cm[2].z = i01; cm[2].w = w01;
                    cm[3].z = i11; cm[3].w = w11;
                    int pr = t >> 1;
#pragma unroll
                    for (int c = 0; c < 4; c++)
                        mb4[pr * 4 + c] = cm[c];
                }
            }
        }
    } else {
        // ---- softmax: head block = wn (64 cols), warp-local over ln ----
#pragma unroll
        for (int i = 0; i < 8; i++) {
            float mx = o[i][0];
#pragma unroll
            for (int j = 1; j < 8; j++) mx = fmaxf(mx, o[i][j]);
            mx = fmaxf(mx, __shfl_xor_sync(0xFFFFFFFFu, mx, 4));
            mx = fmaxf(mx, __shfl_xor_sync(0xFFFFFFFFu, mx, 8));
            mx = fmaxf(mx, __shfl_xor_sync(0xFFFFFFFFu, mx, 16));

            float e[8];
            float s = 0.0f;
#pragma unroll
            for (int j = 0; j < 8; j++) { e[j] = expf(o[i][j] - mx); s += e[j]; }
            s += __shfl_xor_sync(0xFFFFFFFFu, s, 4);
            s += __shfl_xor_sync(0xFFFFFFFFu, s, 8);
            s += __shfl_xor_sync(0xFFFFFFFFu, s, 16);
            float inv = 1.0f / s;

            float* crow = C + (size_t)(m0 + mb + i) * N + n0 + nb;
            *(float4*)(crow)     = make_float4(e[0]*inv, e[1]*inv, e[2]*inv, e[3]*inv);
            *(float4*)(crow + 4) = make_float4(e[4]*inv, e[5]*inv, e[6]*inv, e[7]*inv);
        }
    }
}

// ---------------------------------------------------------------------------
// Output projection GEMM, cp.async 4-stage:
//   C[MQ,256] = midT^T[MQ,256] @ W_out[256,256] + b_out
// Tile 32(M) x 128(N) x BK16; 256 thr; microtile 2m x 8n (warp 4m x 2n,
// warp tile 8m x 64n). 256 CTAs; 3 CTAs/SM.
// ---------------------------------------------------------------------------
#define OT_SA   32
#define OT_STGA (TBK * OT_SA)          // 512 floats
#define OT_STGB (TBK * SBm)            // 3072 floats
#define OT_SMEM (4 * (OT_STGA + OT_STGB) * 4)   // 57344 B

__global__ __launch_bounds__(256, 3) void gemm_out(
    const float* __restrict__ AT,      // [256, MQ]
    const float* __restrict__ B,       // [256, 256]
    const float* __restrict__ bias,
    float* __restrict__ C)             // [MQ, 256]
{
    extern __shared__ __align__(16) float smem[];
    float* As = smem;
    float* Bs = smem + 4 * OT_STGA;

    const int tid  = threadIdx.x;
    const int lane = tid & 31;
    const int wid  = tid >> 5;
    const int wm   = wid & 3;
    const int wn   = wid >> 2;
    const int lm   = lane & 3;
    const int ln   = lane >> 2;
    const int m0   = blockIdx.y * 32;
    const int n0   = blockIdx.x * 128;

    const int aofs = wm * 8 + lm * 2;
    const int bofs = (wn * 8 + ln) * 12;
    const int mb   = aofs;
    const int nb   = wn * 64 + ln * 8;

    auto stage = [&](int sg, int kt) {
        const int k0 = kt * TBK;
        if (tid < 128) {
            int k = tid >> 3, m4 = tid & 7;
            cp16(As + sg * OT_STGA + k * OT_SA + m4 * 4,
                 AT + (size_t)(k0 + k) * MQ + m0 + m4 * 4);
        }
#pragma unroll
        for (int r2 = 0; r2 < 2; r2++) {
            int i = tid + r2 * 256;
            int kk = i >> 5, n4 = i & 31;
            cp16(Bs + sg * OT_STGB + kk * SBm + (n4 >> 1) * 12 + (n4 & 1) * 4,
                 B + (size_t)(k0 + kk) * 256 + n0 + n4 * 4);
        }
    };

    stage(0, 0); CP_COMMIT();
    stage(1, 1); CP_COMMIT();
    stage(2, 2); CP_COMMIT();

    uint64_t acc[2][4];
#pragma unroll
    for (int i = 0; i < 2; i++)
#pragma unroll
        for (int j = 0; j < 4; j++) acc[i][j] = 0ull;

    const int KT = 256 / TBK;   // 16
    int cur = 0;

#pragma unroll 1
    for (int kt = 0; kt < KT; kt++) {
        if (kt <= KT - 3)      { CP_WAIT(2); }
        else if (kt == KT - 2) { CP_WAIT(1); }
        else                   { CP_WAIT(0); }
        __syncthreads();
        if (kt + 3 < KT) {
            stage((kt + 3) & 3, kt + 3);
            CP_COMMIT();
        }

#pragma unroll
        for (int k = 0; k < TBK; k++) {
            float2 a2 = *(const float2*)(As + cur * OT_STGA + k * OT_SA + aofs);
            const uint64_t* bp = (const uint64_t*)(Bs + cur * OT_STGB + k * SBm + bofs);
            uint64_t bd[4];
            bd[0] = bp[0]; bd[1] = bp[1]; bd[2] = bp[2]; bd[3] = bp[3];
            uint64_t ad[2];
            ad[0] = pack2(a2.x, a2.x);
            ad[1] = pack2(a2.y, a2.y);
#pragma unroll
            for (int i = 0; i < 2; i++)
#pragma unroll
                for (int j = 0; j < 4; j++)
                    ffma2(acc[i][j], ad[i], bd[j]);
        }

        cur = (cur + 1) & 3;
    }

    float bn[8];
#pragma unroll
    for (int j = 0; j < 8; j++) bn[j] = __ldg(&bias[n0 + nb + j]);

#pragma unroll
    for (int i = 0; i < 2; i++) {
        float o[8];
#pragma unroll
        for (int j = 0; j < 4; j++)
            unpack2(acc[i][j], o[2 * j], o[2 * j + 1]);
#pragma unroll
        for (int j = 0; j < 8; j++) o[j] += bn[j];
        float* crow = C + (size_t)(m0 + mb + i) * 256 + n0 + nb;
        *(float4*)(crow)     = make_float4(o[0], o[1], o[2], o[3]);
        *(float4*)(crow + 4) = make_float4(o[4], o[5], o[6], o[7]);
    }
}

// ---------------------------------------------------------------------------
// Gather: warp per (b,q,h); 8-sample batches; writes g_midT (k-major scatter).
// ---------------------------------------------------------------------------
__global__ __launch_bounds__(256) void gather_kernel(
    const float* __restrict__ v,
    const float4* __restrict__ meta,
    const float* __restrict__ attn,
    float* __restrict__ midT)
{
    const int bq = blockIdx.x;
    const int b = bq >> 10;
    const int h = threadIdx.x >> 5;
    const int lane = threadIdx.x & 31;
    const int corner = lane >> 3;
    const int cg = lane & 7;

    const float4* m4p = meta + ((size_t)(bq * NH + h) * 32) * 4 + corner;
    const float*  ah  = attn + ((size_t)bq * NH + h) * 64;
    const float*  vb  = v + (size_t)b * LEN_V * EMBED + h * HD + cg * 4;

    float4 acc = make_float4(0.f, 0.f, 0.f, 0.f);

#pragma unroll
    for (int base = 0; base < 64; base += 8) {
        float4 aA = __ldg((const float4*)(ah + base));
        float4 aB = __ldg((const float4*)(ah + base + 4));
        float4 m4[4];
#pragma unroll
        for (int q = 0; q < 4; q++)
            m4[q] = __ldg(&m4p[(base / 2 + q) * 4]);

        float4 vv[8];
#pragma unroll
        for (int q = 0; q < 4; q++) {
            vv[2 * q]     = *(const float4*)(vb + __float_as_int(m4[q].x));
            vv[2 * q + 1] = *(const float4*)(vb + __float_as_int(m4[q].z));
        }

        float a8[8] = {aA.x, aA.y, aA.z, aA.w, aB.x, aB.y, aB.z, aB.w};
#pragma unroll
        for (int q = 0; q < 4; q++) {
            float w0 = m4[q].y * a8[2 * q];
            float w1 = m4[q].w * a8[2 * q + 1];
            acc.x = fmaf(w0, vv[2 * q].x, acc.x);
            acc.y = fmaf(w0, vv[2 * q].y, acc.y);
            acc.z = fmaf(w0, vv[2 * q].z, acc.z);
            acc.w = fmaf(w0, vv[2 * q].w, acc.w);
            acc.x = fmaf(w1, vv[2 * q + 1].x, acc.x);
            acc.y = fmaf(w1, vv[2 * q + 1].y, acc.y);
            acc.z = fmaf(w1, vv[2 * q + 1].z, acc.z);
            acc.w = fmaf(w1, vv[2 * q + 1].w, acc.w);
        }
    }

#pragma unroll
    for (int off = 8; off <= 16; off <<= 1) {
        acc.x += __shfl_xor_sync(0xFFFFFFFFu, acc.x, off);
        acc.y += __shfl_xor_sync(0xFFFFFFFFu, acc.y, off);
        acc.z += __shfl_xor_sync(0xFFFFFFFFu, acc.z, off);
        acc.w += __shfl_xor_sync(0xFFFFFFFFu, acc.w, off);
    }

    if (lane < 8) {
        const int ch = h * HD + cg * 4;
        float* col = midT + bq;
        col[(size_t)(ch + 0) * MQ] = acc.x;
        col[(size_t)(ch + 1) * MQ] = acc.y;
        col[(size_t)(ch + 2) * MQ] = acc.z;
        col[(size_t)(ch + 3) * MQ] = acc.w;
    }
}

// ---------------------------------------------------------------------------
// Launch
// ---------------------------------------------------------------------------
extern "C" void kernel_launch(void* const* d_in, const int* in_sizes, int n_in,
                              void* d_out, int out_size)
{
    const float* query  = (const float*)d_in[0];
    const float* refp   = (const float*)d_in[1];
    const float* value  = (const float*)d_in[2];
    const float* W_val  = (const float*)d_in[3];
    const float* b_val  = (const float*)d_in[4];
    const float* W_off  = (const float*)d_in[5];
    const float* b_off  = (const float*)d_in[6];
    const float* W_attn = (const float*)d_in[7];
    const float* b_attn = (const float*)d_in[8];
    const float* W_out  = (const float*)d_in[9];
    const float* b_out  = (const float*)d_in[10];

    float* out  = (float*)d_out;
    float* loc  = out + LOC_OFFSET;
    float* attn = out + ATTN_OFFSET;

    float* gv;
    float* gmidT;
    float4* gmeta;
    float* gvT;
    float* gqT;
    cudaGetSymbolAddress((void**)&gv, g_v);
    cudaGetSymbolAddress((void**)&gmidT, g_midT);
    cudaGetSymbolAddress((void**)&gmeta, g_meta);
    cudaGetSymbolAddress((void**)&gvT, g_vT);
    cudaGetSymbolAddress((void**)&gqT, g_qT);

    cudaFuncSetAttribute(mega_gemm,
                         cudaFuncAttributeMaxDynamicSharedMemorySize, MEGA_SMEM);
    cudaFuncSetAttribute(gemm_out,
                         cudaFuncAttributeMaxDynamicSharedMemorySize, OT_SMEM);

    // 0. one-shot transpose of value + query (k-major A operands)
    transpose_kernel<<<VT_TILES + QT_TILES, 256>>>(value, query, gvT, gqT);

    // 1. all three front GEMMs in one launch (724 CTAs, 4-stage cp.async)
    mega_gemm<<<MEGA_CTAS, 256, MEGA_SMEM>>>(gvT, gqT, W_val, b_val, W_off, b_off,
                                             W_attn, b_attn, refp, gv, loc, attn, gmeta);

    // 2. batched branchless gather -> g_midT (transposed)
    gather_kernel<<<BS * LQ, 256>>>(gv, gmeta, attn, gmidT);

    // 3. output projection (2 x 128 = 256 CTAs, 4-stage cp.async)
    {
        dim3 grid(EMBED / 128, MQ / 32);
        gemm_out<<<grid, 256, OT_SMEM>>>(gmidT, W_out, b_out, out);
    }
}

// round 16
// speedup vs baseline: 1.0173x; 1.0173x over previous
#include <cuda_runtime.h>
#include <cstdint>

// ---------------------------------------------------------------------------
// Problem constants
// ---------------------------------------------------------------------------
#define BS 4
#define LQ 1024
#define EMBED 256
#define NH 8
#define NL 4
#define NP 16
#define HD 32
#define LEN_V 5440
#define MQ (BS * LQ)        // 4096
#define MV (BS * LEN_V)     // 21760

#define OUT_ELEMS   (BS * LQ * EMBED)
#define LOC_OFFSET  (OUT_ELEMS)
#define LOC_ELEMS   (BS * LQ * NH * NL * NP * 2)
#define ATTN_OFFSET (LOC_OFFSET + LOC_ELEMS)

__constant__ int   c_H[NL]      = {64, 32, 16, 8};
__constant__ int   c_W[NL]      = {64, 32, 16, 8};
__constant__ int   c_start[NL]  = {0, 4096, 5120, 5376};
__constant__ float c_invW[NL]   = {1.0f/64, 1.0f/32, 1.0f/16, 1.0f/8};
__constant__ float c_invH[NL]   = {1.0f/64, 1.0f/32, 1.0f/16, 1.0f/8};

__device__ float  g_v[MV * EMBED];                    // projected value ~22.3 MB
__device__ float  g_midT[EMBED * MQ];                 // pre-W_out, k-major  4 MB
__device__ float4 g_meta[MQ * NH * 32 * 4];           // gather meta     ~67 MB
__device__ float  g_vT[EMBED * MV];                   // value transposed 22.3 MB
__device__ float  g_qT[EMBED * MQ];                   // query transposed  4 MB

// ---------------------------------------------------------------------------
// Packed f32x2 + cp.async helpers
// ---------------------------------------------------------------------------
__device__ __forceinline__ uint64_t pack2(float x, float y) {
    uint64_t r;
    asm("mov.b64 %0, {%1, %2};" : "=l"(r) : "f"(x), "f"(y));
    return r;
}
__device__ __forceinline__ void unpack2(uint64_t v, float& x, float& y) {
    asm("mov.b64 {%0, %1}, %2;" : "=f"(x), "=f"(y) : "l"(v));
}
__device__ __forceinline__ void ffma2(uint64_t& d, uint64_t a, uint64_t b) {
    asm("fma.rn.f32x2 %0, %1, %2, %0;" : "+l"(d) : "l"(a), "l"(b));
}
__device__ __forceinline__ void cp16(void* s, const void* g) {
    uint32_t sa = (uint32_t)__cvta_generic_to_shared(s);
    asm volatile("cp.async.ca.shared.global [%0], [%1], 16;" :: "r"(sa), "l"(g));
}
#define CP_COMMIT() asm volatile("cp.async.commit_group;" ::: "memory")
#define CP_WAIT(N)  asm volatile("cp.async.wait_group %0;" :: "n"(N) : "memory")

// ---------------------------------------------------------------------------
// Transpose kernel: value[MV,256] -> vT[256,MV], query[MQ,256] -> qT[256,MQ]
// ---------------------------------------------------------------------------
#define VT_TILES ((MV / 32) * (EMBED / 32))   // 5440
#define QT_TILES ((MQ / 32) * (EMBED / 32))   // 1024

__global__ __launch_bounds__(256) void transpose_kernel(
    const float* __restrict__ value, const float* __restrict__ query,
    float* __restrict__ vT, float* __restrict__ qT)
{
    __shared__ float tile[32][33];
    int t = blockIdx.x;
    const float* src; float* dst; int Mr, tm, tk;
    if (t < VT_TILES) { src = value; dst = vT; Mr = MV; tm = t >> 3; tk = t & 7; }
    else { t -= VT_TILES; src = query; dst = qT; Mr = MQ; tm = t >> 3; tk = t & 7; }

    const int r  = threadIdx.x >> 3;
    const int c4 = threadIdx.x & 7;

    float4 v = *(const float4*)(src + (size_t)(tm * 32 + r) * EMBED + tk * 32 + c4 * 4);
    tile[r][c4 * 4 + 0] = v.x;
    tile[r][c4 * 4 + 1] = v.y;
    tile[r][c4 * 4 + 2] = v.z;
    tile[r][c4 * 4 + 3] = v.w;
    __syncthreads();

    float4 w;
    w.x = tile[c4 * 4 + 0][r];
    w.y = tile[c4 * 4 + 1][r];
    w.z = tile[c4 * 4 + 2][r];
    w.w = tile[c4 * 4 + 3][r];
    *(float4*)(dst + (size_t)(tk * 32 + r) * Mr + tm * 32 + c4 * 4) = w;
}

// ---------------------------------------------------------------------------
// MEGA GEMM with cp.async 3-stage pipeline (R13/R14 known-good config).
// Tiling: 128x128xBK16, 256 thr, microtile 8x8 (warp 4m x 2n).
// ---------------------------------------------------------------------------
#define TBK  16
#define SAm  128
#define SBm  192
#define STGA (TBK * SAm)               // 2048 floats
#define STGB (TBK * SBm)               // 3072 floats
#define MEGA_SMEM (3 * (STGA + STGB) * 4)   // 61440 B
#define KK   256

#define G3_CTAS 340
#define G1_CTAS 256
#define G2_CTAS 128
#define MEGA_CTAS (G3_CTAS + G1_CTAS + G2_CTAS)

__global__ __launch_bounds__(256, 2) void mega_gemm(
    const float* __restrict__ vT, const float* __restrict__ qT,
    const float* __restrict__ W_val, const float* __restrict__ b_val,
    const float* __restrict__ W_off, const float* __restrict__ b_off,
    const float* __restrict__ W_attn, const float* __restrict__ b_attn,
    const float* __restrict__ refp,
    float* __restrict__ gv, float* __restrict__ loc,
    float* __restrict__ attn_out, float4* __restrict__ meta)
{
    extern __shared__ __align__(16) float smem[];
    float* As = smem;
    float* Bs = smem + 3 * STGA;

    const int cta = blockIdx.x;
    const float *AT, *B, *bias;
    float* C;
    int N, mode, gx, gy, Mlen;
    if (cta < G3_CTAS) {
        AT = vT; Mlen = MV; B = W_val; bias = b_val; C = gv;
        N = 256; mode = 0; gx = cta & 1; gy = cta >> 1;
    } else if (cta < G3_CTAS + G1_CTAS) {
        int l = cta - G3_CTAS;
        AT = qT; Mlen = MQ; B = W_off; bias = b_off; C = loc;
        N = 1024; mode = 1; gx = l & 7; gy = l >> 3;
    } else {
        int l = cta - (G3_CTAS + G1_CTAS);
        AT = qT; Mlen = MQ; B = W_attn; bias = b_attn; C = attn_out;
        N = 512; mode = 2; gx = l & 3; gy = l >> 2;
    }
    const int m0 = gy * 128;
    const int n0 = gx * 128;

    const int tid  = threadIdx.x;
    const int lane = tid & 31;
    const int wid  = tid >> 5;
    const int wm   = wid & 3;
    const int wn   = wid >> 2;
    const int lm   = lane & 3;
    const int ln   = lane >> 2;

    const int aofs = wm * 32 + lm * 8;
    const int bofs = (wn * 8 + ln) * 12;
    const int mb   = wm * 32 + lm * 8;
    const int nb   = wn * 64 + ln * 8;

    auto stage = [&](int sg, int kt) {
        const int k0 = kt * TBK;
#pragma unroll
        for (int r2 = 0; r2 < 2; r2++) {
            int i = tid + r2 * 256;
            int k = i >> 5, m4 = i & 31;
            cp16(As + sg * STGA + k * SAm + m4 * 4,
                 AT + (size_t)(k0 + k) * Mlen + m0 + m4 * 4);
        }
#pragma unroll
        for (int r2 = 0; r2 < 2; r2++) {
            int i = tid + r2 * 256;
            int kk = i >> 5, n4 = i & 31;
            cp16(Bs + sg * STGB + kk * SBm + (n4 >> 1) * 12 + (n4 & 1) * 4,
                 B + (size_t)(k0 + kk) * N + n0 + n4 * 4);
        }
    };

    stage(0, 0); CP_COMMIT();
    stage(1, 1); CP_COMMIT();

    uint64_t acc[8][4];
#pragma unroll
    for (int i = 0; i < 8; i++)
#pragma unroll
        for (int j = 0; j < 4; j++) acc[i][j] = 0ull;

    const int KT = KK / TBK;
    int cur = 0;

#pragma unroll 1
    for (int kt = 0; kt < KT; kt++) {
        if (kt + 1 < KT) { CP_WAIT(1); } else { CP_WAIT(0); }
        __syncthreads();
        if (kt + 2 < KT) {
            stage((kt + 2) % 3, kt + 2);
            CP_COMMIT();
        }

#pragma unroll
        for (int k = 0; k < TBK; k++) {
            const float* ap = As + cur * STGA + k * SAm + aofs;
            float4 a0 = *(const float4*)(ap);
            float4 a1 = *(const float4*)(ap + 4);
            const uint64_t* bp = (const uint64_t*)(Bs + cur * STGB + k * SBm + bofs);
            uint64_t bd[4];
            bd[0] = bp[0]; bd[1] = bp[1]; bd[2] = bp[2]; bd[3] = bp[3];
            uint64_t ad[8];
            ad[0] = pack2(a0.x, a0.x);
            ad[1] = pack2(a0.y, a0.y);
            ad[2] = pack2(a0.z, a0.z);
            ad[3] = pack2(a0.w, a0.w);
            ad[4] = pack2(a1.x, a1.x);
            ad[5] = pack2(a1.y, a1.y);
            ad[6] = pack2(a1.z, a1.z);
            ad[7] = pack2(a1.w, a1.w);
#pragma unroll
            for (int i = 0; i < 8; i++)
#pragma unroll
                for (int j = 0; j < 4; j++)
                    ffma2(acc[i][j], ad[i], bd[j]);
        }

        cur++;
        if (cur == 3) cur = 0;
    }

    float bn[8];
#pragma unroll
    for (int j = 0; j < 8; j++) bn[j] = __ldg(&bias[n0 + nb + j]);

    float o[8][8];
#pragma unroll
    for (int i = 0; i < 8; i++) {
#pragma unroll
        for (int j = 0; j < 4; j++)
            unpack2(acc[i][j], o[i][2 * j], o[i][2 * j + 1]);
#pragma unroll
        for (int j = 0; j < 8; j++) o[i][j] += bn[j];
    }

    if (mode == 0) {
#pragma unroll
        for (int i = 0; i < 8; i++) {
            float* crow = C + (size_t)(m0 + mb + i) * N + n0 + nb;
            *(float4*)(crow)     = make_float4(o[i][0], o[i][1], o[i][2], o[i][3]);
            *(float4*)(crow + 4) = make_float4(o[i][4], o[i][5], o[i][6], o[i][7]);
        }
    } else if (mode == 1) {
        // ---- sampling-location transform + gather-meta (pair-corner layout) ----
        __syncthreads();
        float* rps = As;
        {
            int row = tid >> 1, half = tid & 1;
            *(float4*)(rps + row * 8 + half * 4) =
                *(const float4*)(refp + (size_t)(m0 + row) * 8 + half * 4);
        }
        __syncthreads();

        const int h = gx;
        const int lvl = wn * 2 + (ln >> 2);
        const int W = c_W[lvl], H = c_H[lvl];
        const float fW = (float)W, fH = (float)H;
        const float invW = c_invW[lvl], invH = c_invH[lvl];
        const int cstE = c_start[lvl] * EMBED;
        const int pbase = (ln & 3) * 4;

#pragma unroll
        for (int i = 0; i < 8; i++) {
            const int bq = m0 + mb + i;
            const float* rp = rps + (mb + i) * 8;
            float rx0 = rp[0], rx1 = rp[1], rx2 = rp[2], rx3 = rp[3];
            float ry0 = rp[4], ry1 = rp[5], ry2 = rp[6], ry3 = rp[7];
            float res[8];
#pragma unroll
            for (int j = 0; j < 8; j++) {
                int p = pbase + (j >> 1);
                int c = j & 1;
                float lam = (float)p * (1.0f / 15.0f);
                float pnt = c ? (((ry0 * lam + ry1) * lam + ry2) * lam + ry3)
                              : (((rx0 * lam + rx1) * lam + rx2) * lam + rx3);
                float inv = c ? invH : invW;
                res[j] = pnt + o[i][j] * inv;
            }
            float* crow = C + (size_t)bq * N + n0 + nb;
            *(float4*)(crow)     = make_float4(res[0], res[1], res[2], res[3]);
            *(float4*)(crow + 4) = make_float4(res[4], res[5], res[6], res[7]);

            float4 cm[4];
            float4* mb4 = meta + ((size_t)(bq * NH + h) * 32 + lvl * 8 + (pbase >> 1)) * 4;
#pragma unroll
            for (int t = 0; t < 4; t++) {
                float x = res[2 * t]     * fW - 0.5f;
                float y = res[2 * t + 1] * fH - 0.5f;
                float x0f = floorf(x);
                float y0f = floorf(y);
                float wx = x - x0f;
                float wy = y - y0f;
                int x0 = (int)x0f, y0 = (int)y0f;
                int x1 = x0 + 1,   y1 = y0 + 1;

                bool vx0 = (x0 >= 0) & (x0 < W);
                bool vx1 = (x1 >= 0) & (x1 < W);
                bool vy0 = (y0 >= 0) & (y0 < H);
                bool vy1 = (y1 >= 0) & (y1 < H);

                float w00 = (vx0 & vy0) ? (1.0f - wx) * (1.0f - wy) : 0.0f;
                float w10 = (vx1 & vy0) ? wx * (1.0f - wy)          : 0.0f;
                float w01 = (vx0 & vy1) ? (1.0f - wx) * wy          : 0.0f;
                float w11 = (vx1 & vy1) ? wx * wy                   : 0.0f;

                int cx0 = min(max(x0, 0), W - 1);
                int cx1 = min(max(x1, 0), W - 1);
                int cy0 = min(max(y0, 0), H - 1);
                int cy1 = min(max(y1, 0), H - 1);

                float i00 = __int_as_float(cstE + (cy0 * W + cx0) * EMBED);
                float i10 = __int_as_float(cstE + (cy0 * W + cx1) * EMBED);
                float i01 = __int_as_float(cstE + (cy1 * W + cx0) * EMBED);
                float i11 = __int_as_float(cstE + (cy1 * W + cx1) * EMBED);

                if ((t & 1) == 0) {
                    cm[0].x = i00; cm[0].y = w00;
                    cm[1].x = i10; cm[1].y = w10;
                    cm[2].x = i01; cm[2].y = w01;
                    cm[3].x = i11; cm[3].y = w11;
                } else {
                    cm[0].z = i00; cm[0].w = w00;
                    cm[1].z = i10; cm[1].w = w10;
                    cm[2].z = i01; cm[2].w = w01;
                    cm[3].z = i11; cm[3].w = w11;
                    int pr = t >> 1;
#pragma unroll
                    for (int c = 0; c < 4; c++)
                        mb4[pr * 4 + c] = cm[c];
                }
            }
        }
    } else {
        // ---- softmax: head block = wn (64 cols), warp-local over ln ----
#pragma unroll
        for (int i = 0; i < 8; i++) {
            float mx = o[i][0];
#pragma unroll
            for (int j = 1; j < 8; j++) mx = fmaxf(mx, o[i][j]);
            mx = fmaxf(mx, __shfl_xor_sync(0xFFFFFFFFu, mx, 4));
            mx = fmaxf(mx, __shfl_xor_sync(0xFFFFFFFFu, mx, 8));
            mx = fmaxf(mx, __shfl_xor_sync(0xFFFFFFFFu, mx, 16));

            float e[8];
            float s = 0.0f;
#pragma unroll
            for (int j = 0; j < 8; j++) { e[j] = expf(o[i][j] - mx); s += e[j]; }
            s += __shfl_xor_sync(0xFFFFFFFFu, s, 4);
            s += __shfl_xor_sync(0xFFFFFFFFu, s, 8);
            s += __shfl_xor_sync(0xFFFFFFFFu, s, 16);
            float inv = 1.0f / s;

            float* crow = C + (size_t)(m0 + mb + i) * N + n0 + nb;
            *(float4*)(crow)     = make_float4(e[0]*inv, e[1]*inv, e[2]*inv, e[3]*inv);
            *(float4*)(crow + 4) = make_float4(e[4]*inv, e[5]*inv, e[6]*inv, e[7]*inv);
        }
    }
}

// ---------------------------------------------------------------------------
// Output projection GEMM, cp.async 4-stage, TBM=64 (B-reuse preserved):
//   C[MQ,256] = midT^T[MQ,256] @ W_out[256,256] + b_out
// Tile 64(M) x 128(N) x BK16; 256 thr; microtile 4m x 8n. 128 CTAs.
// ---------------------------------------------------------------------------
#define OT_SA   64
#define OT_STGA (TBK * OT_SA)          // 1024 floats
#define OT_STGB (TBK * SBm)            // 3072 floats
#define OT_SMEM (4 * (OT_STGA + OT_STGB) * 4)   // 65536 B

__global__ __launch_bounds__(256, 2) void gemm_out(
    const float* __restrict__ AT,      // [256, MQ]
    const float* __restrict__ B,       // [256, 256]
    const float* __restrict__ bias,
    float* __restrict__ C)             // [MQ, 256]
{
    extern __shared__ __align__(16) float smem[];
    float* As = smem;
    float* Bs = smem + 4 * OT_STGA;

    const int tid  = threadIdx.x;
    const int lane = tid & 31;
    const int wid  = tid >> 5;
    const int wm   = wid & 3;
    const int wn   = wid >> 2;
    const int lm   = lane & 3;
    const int ln   = lane >> 2;
    const int m0   = blockIdx.y * 64;
    const int n0   = blockIdx.x * 128;

    const int aofs = wm * 16 + lm * 4;
    const int bofs = (wn * 8 + ln) * 12;
    const int mb   = aofs;
    const int nb   = wn * 64 + ln * 8;

    auto stage = [&](int sg, int kt) {
        const int k0 = kt * TBK;
        {
            int k = tid >> 4, m4 = tid & 15;
            cp16(As + sg * OT_STGA + k * OT_SA + m4 * 4,
                 AT + (size_t)(k0 + k) * MQ + m0 + m4 * 4);
        }
#pragma unroll
        for (int r2 = 0; r2 < 2; r2++) {
            int i = tid + r2 * 256;
            int kk = i >> 5, n4 = i & 31;
            cp16(Bs + sg * OT_STGB + kk * SBm + (n4 >> 1) * 12 + (n4 & 1) * 4,
                 B + (size_t)(k0 + kk) * 256 + n0 + n4 * 4);
        }
    };

    stage(0, 0); CP_COMMIT();
    stage(1, 1); CP_COMMIT();
    stage(2, 2); CP_COMMIT();

    uint64_t acc[4][4];
#pragma unroll
    for (int i = 0; i < 4; i++)
#pragma unroll
        for (int j = 0; j < 4; j++) acc[i][j] = 0ull;

    const int KT = 256 / TBK;   // 16
    int cur = 0;

#pragma unroll 1
    for (int kt = 0; kt < KT; kt++) {
        if (kt <= KT - 4)      { CP_WAIT(2); }
        else if (kt == KT - 3) { CP_WAIT(2); }
        else if (kt == KT - 2) { CP_WAIT(1); }
        else                   { CP_WAIT(0); }
        __syncthreads();
        if (kt + 3 < KT) {
            stage((kt + 3) & 3, kt + 3);
            CP_COMMIT();
        }

#pragma unroll
        for (int k = 0; k < TBK; k++) {
            float4 a4 = *(const float4*)(As + cur * OT_STGA + k * OT_SA + aofs);
            const uint64_t* bp = (const uint64_t*)(Bs + cur * OT_STGB + k * SBm + bofs);
            uint64_t bd[4];
            bd[0] = bp[0]; bd[1] = bp[1]; bd[2] = bp[2]; bd[3] = bp[3];
            uint64_t ad[4];
            ad[0] = pack2(a4.x, a4.x);
            ad[1] = pack2(a4.y, a4.y);
            ad[2] = pack2(a4.z, a4.z);
            ad[3] = pack2(a4.w, a4.w);
#pragma unroll
            for (int i = 0; i < 4; i++)
#pragma unroll
                for (int j = 0; j < 4; j++)
                    ffma2(acc[i][j], ad[i], bd[j]);
        }

        cur = (cur + 1) & 3;
    }

    float bn[8];
#pragma unroll
    for (int j = 0; j < 8; j++) bn[j] = __ldg(&bias[n0 + nb + j]);

#pragma unroll
    for (int i = 0; i < 4; i++) {
        float o[8];
#pragma unroll
        for (int j = 0; j < 4; j++)
            unpack2(acc[i][j], o[2 * j], o[2 * j + 1]);
#pragma unroll
        for (int j = 0; j < 8; j++) o[j] += bn[j];
        float* crow = C + (size_t)(m0 + mb + i) * 256 + n0 + nb;
        *(float4*)(crow)     = make_float4(o[0], o[1], o[2], o[3]);
        *(float4*)(crow + 4) = make_float4(o[4], o[5], o[6], o[7]);
    }
}

// ---------------------------------------------------------------------------
// Gather: warp per (b,q,h); 8-sample batches; writes g_midT (k-major scatter).
// ---------------------------------------------------------------------------
__global__ __launch_bounds__(256) void gather_kernel(
    const float* __restrict__ v,
    const float4* __restrict__ meta,
    const float* __restrict__ attn,
    float* __restrict__ midT)
{
    const int bq = blockIdx.x;
    const int b = bq >> 10;
    const int h = threadIdx.x >> 5;
    const int lane = threadIdx.x & 31;
    const int corner = lane >> 3;
    const int cg = lane & 7;

    const float4* m4p = meta + ((size_t)(bq * NH + h) * 32) * 4 + corner;
    const float*  ah  = attn + ((size_t)bq * NH + h) * 64;
    const float*  vb  = v + (size_t)b * LEN_V * EMBED + h * HD + cg * 4;

    float4 acc = make_float4(0.f, 0.f, 0.f, 0.f);

#pragma unroll
    for (int base = 0; base < 64; base += 8) {
        float4 aA = __ldg((const float4*)(ah + base));
        float4 aB = __ldg((const float4*)(ah + base + 4));
        float4 m4[4];
#pragma unroll
        for (int q = 0; q < 4; q++)
            m4[q] = __ldg(&m4p[(base / 2 + q) * 4]);

        float4 vv[8];
#pragma unroll
        for (int q = 0; q < 4; q++) {
            vv[2 * q]     = *(const float4*)(vb + __float_as_int(m4[q].x));
            vv[2 * q + 1] = *(const float4*)(vb + __float_as_int(m4[q].z));
        }

        float a8[8] = {aA.x, aA.y, aA.z, aA.w, aB.x, aB.y, aB.z, aB.w};
#pragma unroll
        for (int q = 0; q < 4; q++) {
            float w0 = m4[q].y * a8[2 * q];
            float w1 = m4[q].w * a8[2 * q + 1];
            acc.x = fmaf(w0, vv[2 * q].x, acc.x);
            acc.y = fmaf(w0, vv[2 * q].y, acc.y);
            acc.z = fmaf(w0, vv[2 * q].z, acc.z);
            acc.w = fmaf(w0, vv[2 * q].w, acc.w);
            acc.x = fmaf(w1, vv[2 * q + 1].x, acc.x);
            acc.y = fmaf(w1, vv[2 * q + 1].y, acc.y);
            acc.z = fmaf(w1, vv[2 * q + 1].z, acc.z);
            acc.w = fmaf(w1, vv[2 * q + 1].w, acc.w);
        }
    }

#pragma unroll
    for (int off = 8; off <= 16; off <<= 1) {
        acc.x += __shfl_xor_sync(0xFFFFFFFFu, acc.x, off);
        acc.y += __shfl_xor_sync(0xFFFFFFFFu, acc.y, off);
        acc.z += __shfl_xor_sync(0xFFFFFFFFu, acc.z, off);
        acc.w += __shfl_xor_sync(0xFFFFFFFFu, acc.w, off);
    }

    if (lane < 8) {
        const int ch = h * HD + cg * 4;
        float* col = midT + bq;
        col[(size_t)(ch + 0) * MQ] = acc.x;
        col[(size_t)(ch + 1) * MQ] = acc.y;
        col[(size_t)(ch + 2) * MQ] = acc.z;
        col[(size_t)(ch + 3) * MQ] = acc.w;
    }
}

// ---------------------------------------------------------------------------
// Launch
// ---------------------------------------------------------------------------
extern "C" void kernel_launch(void* const* d_in, const int* in_sizes, int n_in,
                              void* d_out, int out_size)
{
    const float* query  = (const float*)d_in[0];
    const float* refp   = (const float*)d_in[1];
    const float* value  = (const float*)d_in[2];
    const float* W_val  = (const float*)d_in[3];
    const float* b_val  = (const float*)d_in[4];
    const float* W_off  = (const float*)d_in[5];
    const float* b_off  = (const float*)d_in[6];
    const float* W_attn = (const float*)d_in[7];
    const float* b_attn = (const float*)d_in[8];
    const float* W_out  = (const float*)d_in[9];
    const float* b_out  = (const float*)d_in[10];

    float* out  = (float*)d_out;
    float* loc  = out + LOC_OFFSET;
    float* attn = out + ATTN_OFFSET;

    float* gv;
    float* gmidT;
    float4* gmeta;
    float* gvT;
    float* gqT;
    cudaGetSymbolAddress((void**)&gv, g_v);
    cudaGetSymbolAddress((void**)&gmidT, g_midT);
    cudaGetSymbolAddress((void**)&gmeta, g_meta);
    cudaGetSymbolAddress((void**)&gvT, g_vT);
    cudaGetSymbolAddress((void**)&gqT, g_qT);

    cudaFuncSetAttribute(mega_gemm,
                         cudaFuncAttributeMaxDynamicSharedMemorySize, MEGA_SMEM);
    cudaFuncSetAttribute(gemm_out,
                         cudaFuncAttributeMaxDynamicSharedMemorySize, OT_SMEM);

    // 0. one-shot transpose of value + query (k-major A operands)
    transpose_kernel<<<VT_TILES + QT_TILES, 256>>>(value, query, gvT, gqT);

    // 1. all three front GEMMs in one launch (724 CTAs, 3-stage cp.async)
    mega_gemm<<<MEGA_CTAS, 256, MEGA_SMEM>>>(gvT, gqT, W_val, b_val, W_off, b_off,
                                             W_attn, b_attn, refp, gv, loc, attn, gmeta);

    // 2. batched branchless gather -> g_midT (transposed)
    gather_kernel<<<BS * LQ, 256>>>(gv, gmeta, attn, gmidT);

    // 3. output projection (2 x 64 = 128 CTAs, 4-stage cp.async, TBM=64)
    {
        dim3 grid(EMBED / 128, MQ / 64);
        gemm_out<<<grid, 256, OT_SMEM>>>(gmidT, W_out, b_out, out);
    }
}

// round 17
// speedup vs baseline: 1.0221x; 1.0047x over previous
#include <cuda_runtime.h>
#include <cstdint>

// ---------------------------------------------------------------------------
// Problem constants
// ---------------------------------------------------------------------------
#define BS 4
#define LQ 1024
#define EMBED 256
#define NH 8
#define NL 4
#define NP 16
#define HD 32
#define LEN_V 5440
#define MQ (BS * LQ)        // 4096
#define MV (BS * LEN_V)     // 21760

#define OUT_ELEMS   (BS * LQ * EMBED)
#define LOC_OFFSET  (OUT_ELEMS)
#define LOC_ELEMS   (BS * LQ * NH * NL * NP * 2)
#define ATTN_OFFSET (LOC_OFFSET + LOC_ELEMS)

__constant__ int   c_H[NL]      = {64, 32, 16, 8};
__constant__ int   c_W[NL]      = {64, 32, 16, 8};
__constant__ int   c_start[NL]  = {0, 4096, 5120, 5376};
__constant__ float c_invW[NL]   = {1.0f/64, 1.0f/32, 1.0f/16, 1.0f/8};
__constant__ float c_invH[NL]   = {1.0f/64, 1.0f/32, 1.0f/16, 1.0f/8};

__device__ float  g_v[MV * EMBED];                    // projected value ~22.3 MB
__device__ float  g_midT[EMBED * MQ];                 // pre-W_out, k-major  4 MB
__device__ float4 g_meta[MQ * NH * 32 * 4];           // gather meta     ~67 MB
__device__ float  g_vT[EMBED * MV];                   // value transposed 22.3 MB
__device__ float  g_qT[EMBED * MQ];                   // query transposed  4 MB

// ---------------------------------------------------------------------------
// Packed f32x2 + cp.async helpers
// ---------------------------------------------------------------------------
__device__ __forceinline__ uint64_t pack2(float x, float y) {
    uint64_t r;
    asm("mov.b64 %0, {%1, %2};" : "=l"(r) : "f"(x), "f"(y));
    return r;
}
__device__ __forceinline__ void unpack2(uint64_t v, float& x, float& y) {
    asm("mov.b64 {%0, %1}, %2;" : "=f"(x), "=f"(y) : "l"(v));
}
__device__ __forceinline__ void ffma2(uint64_t& d, uint64_t a, uint64_t b) {
    asm("fma.rn.f32x2 %0, %1, %2, %0;" : "+l"(d) : "l"(a), "l"(b));
}
__device__ __forceinline__ void cp16(void* s, const void* g) {
    uint32_t sa = (uint32_t)__cvta_generic_to_shared(s);
    asm volatile("cp.async.ca.shared.global [%0], [%1], 16;" :: "r"(sa), "l"(g));
}
#define CP_COMMIT() asm volatile("cp.async.commit_group;" ::: "memory")
#define CP_WAIT(N)  asm volatile("cp.async.wait_group %0;" :: "n"(N) : "memory")

// ---------------------------------------------------------------------------
// Transpose kernel: value[MV,256] -> vT[256,MV], query[MQ,256] -> qT[256,MQ]
// ---------------------------------------------------------------------------
#define VT_TILES ((MV / 32) * (EMBED / 32))   // 5440
#define QT_TILES ((MQ / 32) * (EMBED / 32))   // 1024

__global__ __launch_bounds__(256) void transpose_kernel(
    const float* __restrict__ value, const float* __restrict__ query,
    float* __restrict__ vT, float* __restrict__ qT)
{
    __shared__ float tile[32][33];
    int t = blockIdx.x;
    const float* src; float* dst; int Mr, tm, tk;
    if (t < VT_TILES) { src = value; dst = vT; Mr = MV; tm = t >> 3; tk = t & 7; }
    else { t -= VT_TILES; src = query; dst = qT; Mr = MQ; tm = t >> 3; tk = t & 7; }

    const int r  = threadIdx.x >> 3;
    const int c4 = threadIdx.x & 7;

    float4 v = *(const float4*)(src + (size_t)(tm * 32 + r) * EMBED + tk * 32 + c4 * 4);
    tile[r][c4 * 4 + 0] = v.x;
    tile[r][c4 * 4 + 1] = v.y;
    tile[r][c4 * 4 + 2] = v.z;
    tile[r][c4 * 4 + 3] = v.w;
    __syncthreads();

    float4 w;
    w.x = tile[c4 * 4 + 0][r];
    w.y = tile[c4 * 4 + 1][r];
    w.z = tile[c4 * 4 + 2][r];
    w.w = tile[c4 * 4 + 3][r];
    *(float4*)(dst + (size_t)(tk * 32 + r) * Mr + tm * 32 + c4 * 4) = w;
}

// ---------------------------------------------------------------------------
// MEGA GEMM: TBK=32, 2-buffer cp.async pipeline (8 iterations, 8 barriers).
// Tiling: 128x128xBK32, 256 thr, microtile 8x8 (warp 4m x 2n).
// ---------------------------------------------------------------------------
#define TBKM 32
#define SAm  128
#define SBm  192
#define STGA (TBKM * SAm)              // 4096 floats (16 KB)
#define STGB (TBKM * SBm)              // 6144 floats (24 KB)
#define MEGA_SMEM (2 * (STGA + STGB) * 4)   // 81920 B
#define KK   256

#define G3_CTAS 340
#define G1_CTAS 256
#define G2_CTAS 128
#define MEGA_CTAS (G3_CTAS + G1_CTAS + G2_CTAS)

__global__ __launch_bounds__(256, 2) void mega_gemm(
    const float* __restrict__ vT, const float* __restrict__ qT,
    const float* __restrict__ W_val, const float* __restrict__ b_val,
    const float* __restrict__ W_off, const float* __restrict__ b_off,
    const float* __restrict__ W_attn, const float* __restrict__ b_attn,
    const float* __restrict__ refp,
    float* __restrict__ gv, float* __restrict__ loc,
    float* __restrict__ attn_out, float4* __restrict__ meta)
{
    extern __shared__ __align__(16) float smem[];
    float* As = smem;                  // 2 buffers x STGA
    float* Bs = smem + 2 * STGA;       // 2 buffers x STGB

    const int cta = blockIdx.x;
    const float *AT, *B, *bias;
    float* C;
    int N, mode, gx, gy, Mlen;
    if (cta < G3_CTAS) {
        AT = vT; Mlen = MV; B = W_val; bias = b_val; C = gv;
        N = 256; mode = 0; gx = cta & 1; gy = cta >> 1;
    } else if (cta < G3_CTAS + G1_CTAS) {
        int l = cta - G3_CTAS;
        AT = qT; Mlen = MQ; B = W_off; bias = b_off; C = loc;
        N = 1024; mode = 1; gx = l & 7; gy = l >> 3;
    } else {
        int l = cta - (G3_CTAS + G1_CTAS);
        AT = qT; Mlen = MQ; B = W_attn; bias = b_attn; C = attn_out;
        N = 512; mode = 2; gx = l & 3; gy = l >> 2;
    }
    const int m0 = gy * 128;
    const int n0 = gx * 128;

    const int tid  = threadIdx.x;
    const int lane = tid & 31;
    const int wid  = tid >> 5;
    const int wm   = wid & 3;
    const int wn   = wid >> 2;
    const int lm   = lane & 3;
    const int ln   = lane >> 2;

    const int aofs = wm * 32 + lm * 8;
    const int bofs = (wn * 8 + ln) * 12;
    const int mb   = wm * 32 + lm * 8;
    const int nb   = wn * 64 + ln * 8;

    // stage one TBKM-deep tile (A: 1024 chunks, B: 1024 chunks; 4 each/thread)
    auto stage = [&](int sg, int kt) {
        const int k0 = kt * TBKM;
#pragma unroll
        for (int r2 = 0; r2 < 4; r2++) {
            int i = tid + r2 * 256;
            int k = i >> 5, m4 = i & 31;
            cp16(As + sg * STGA + k * SAm + m4 * 4,
                 AT + (size_t)(k0 + k) * Mlen + m0 + m4 * 4);
        }
#pragma unroll
        for (int r2 = 0; r2 < 4; r2++) {
            int i = tid + r2 * 256;
            int kk = i >> 5, n4 = i & 31;
            cp16(Bs + sg * STGB + kk * SBm + (n4 >> 1) * 12 + (n4 & 1) * 4,
                 B + (size_t)(k0 + kk) * N + n0 + n4 * 4);
        }
    };

    stage(0, 0); CP_COMMIT();

    uint64_t acc[8][4];
#pragma unroll
    for (int i = 0; i < 8; i++)
#pragma unroll
        for (int j = 0; j < 4; j++) acc[i][j] = 0ull;

    const int KT = KK / TBKM;   // 8

#pragma unroll 1
    for (int kt = 0; kt < KT; kt++) {
        const int cur = kt & 1;
        CP_WAIT(0);              // tile kt arrived
        __syncthreads();         // everyone done reading the other buffer
        if (kt + 1 < KT) {
            stage(cur ^ 1, kt + 1);
            CP_COMMIT();
        }

#pragma unroll
        for (int k = 0; k < TBKM; k++) {
            const float* ap = As + cur * STGA + k * SAm + aofs;
            float4 a0 = *(const float4*)(ap);
            float4 a1 = *(const float4*)(ap + 4);
            const uint64_t* bp = (const uint64_t*)(Bs + cur * STGB + k * SBm + bofs);
            uint64_t bd[4];
            bd[0] = bp[0]; bd[1] = bp[1]; bd[2] = bp[2]; bd[3] = bp[3];
            uint64_t ad[8];
            ad[0] = pack2(a0.x, a0.x);
            ad[1] = pack2(a0.y, a0.y);
            ad[2] = pack2(a0.z, a0.z);
            ad[3] = pack2(a0.w, a0.w);
            ad[4] = pack2(a1.x, a1.x);
            ad[5] = pack2(a1.y, a1.y);
            ad[6] = pack2(a1.z, a1.z);
            ad[7] = pack2(a1.w, a1.w);
#pragma unroll
            for (int i = 0; i < 8; i++)
#pragma unroll
                for (int j = 0; j < 4; j++)
                    ffma2(acc[i][j], ad[i], bd[j]);
        }
    }

    float bn[8];
#pragma unroll
    for (int j = 0; j < 8; j++) bn[j] = __ldg(&bias[n0 + nb + j]);

    float o[8][8];
#pragma unroll
    for (int i = 0; i < 8; i++) {
#pragma unroll
        for (int j = 0; j < 4; j++)
            unpack2(acc[i][j], o[i][2 * j], o[i][2 * j + 1]);
#pragma unroll
        for (int j = 0; j < 8; j++) o[i][j] += bn[j];
    }

    if (mode == 0) {
#pragma unroll
        for (int i = 0; i < 8; i++) {
            float* crow = C + (size_t)(m0 + mb + i) * N + n0 + nb;
            *(float4*)(crow)     = make_float4(o[i][0], o[i][1], o[i][2], o[i][3]);
            *(float4*)(crow + 4) = make_float4(o[i][4], o[i][5], o[i][6], o[i][7]);
        }
    } else if (mode == 1) {
        // ---- sampling-location transform + gather-meta (pair-corner layout) ----
        __syncthreads();
        float* rps = As;
        {
            int row = tid >> 1, half = tid & 1;
            *(float4*)(rps + row * 8 + half * 4) =
                *(const float4*)(refp + (size_t)(m0 + row) * 8 + half * 4);
        }
        __syncthreads();

        const int h = gx;
        const int lvl = wn * 2 + (ln >> 2);
        const int W = c_W[lvl], H = c_H[lvl];
        const float fW = (float)W, fH = (float)H;
        const float invW = c_invW[lvl], invH = c_invH[lvl];
        const int cstE = c_start[lvl] * EMBED;
        const int pbase = (ln & 3) * 4;

#pragma unroll
        for (int i = 0; i < 8; i++) {
            const int bq = m0 + mb + i;
            const float* rp = rps + (mb + i) * 8;
            float rx0 = rp[0], rx1 = rp[1], rx2 = rp[2], rx3 = rp[3];
            float ry0 = rp[4], ry1 = rp[5], ry2 = rp[6], ry3 = rp[7];
            float res[8];
#pragma unroll
            for (int j = 0; j < 8; j++) {
                int p = pbase + (j >> 1);
                int c = j & 1;
                float lam = (float)p * (1.0f / 15.0f);
                float pnt = c ? (((ry0 * lam + ry1) * lam + ry2) * lam + ry3)
                              : (((rx0 * lam + rx1) * lam + rx2) * lam + rx3);
                float inv = c ? invH : invW;
                res[j] = pnt + o[i][j] * inv;
            }
            float* crow = C + (size_t)bq * N + n0 + nb;
            *(float4*)(crow)     = make_float4(res[0], res[1], res[2], res[3]);
            *(float4*)(crow + 4) = make_float4(res[4], res[5], res[6], res[7]);

            float4 cm[4];
            float4* mb4 = meta + ((size_t)(bq * NH + h) * 32 + lvl * 8 + (pbase >> 1)) * 4;
#pragma unroll
            for (int t = 0; t < 4; t++) {
                float x = res[2 * t]     * fW - 0.5f;
                float y = res[2 * t + 1] * fH - 0.5f;
                float x0f = floorf(x);
                float y0f = floorf(y);
                float wx = x - x0f;
                float wy = y - y0f;
                int x0 = (int)x0f, y0 = (int)y0f;
                int x1 = x0 + 1,   y1 = y0 + 1;

                bool vx0 = (x0 >= 0) & (x0 < W);
                bool vx1 = (x1 >= 0) & (x1 < W);
                bool vy0 = (y0 >= 0) & (y0 < H);
                bool vy1 = (y1 >= 0) & (y1 < H);

                float w00 = (vx0 & vy0) ? (1.0f - wx) * (1.0f - wy) : 0.0f;
                float w10 = (vx1 & vy0) ? wx * (1.0f - wy)          : 0.0f;
                float w01 = (vx0 & vy1) ? (1.0f - wx) * wy          : 0.0f;
                float w11 = (vx1 & vy1) ? wx * wy                   : 0.0f;

                int cx0 = min(max(x0, 0), W - 1);
                int cx1 = min(max(x1, 0), W - 1);
                int cy0 = min(max(y0, 0), H - 1);
                int cy1 = min(max(y1, 0), H - 1);

                float i00 = __int_as_float(cstE + (cy0 * W + cx0) * EMBED);
                float i10 = __int_as_float(cstE + (cy0 * W + cx1) * EMBED);
                float i01 = __int_as_float(cstE + (cy1 * W + cx0) * EMBED);
                float i11 = __int_as_float(cstE + (cy1 * W + cx1) * EMBED);

                if ((t & 1) == 0) {
                    cm[0].x = i00; cm[0].y = w00;
                    cm[1].x = i10; cm[1].y = w10;
                    cm[2].x = i01; cm[2].y = w01;
                    cm[3].x = i11; cm[3].y = w11;
                } else {
                    cm[0].z = i00; cm[0].w = w00;
                    cm[1].z = i10; cm[1].w = w10;
                    cm[2].z = i01; cm[2].w = w01;
                    cm[3].z = i11; cm[3].w = w11;
                    int pr = t >> 1;
#pragma unroll
                    for (int c = 0; c < 4; c++)
                        mb4[pr * 4 + c] = cm[c];
                }
            }
        }
    } else {
        // ---- softmax: head block = wn (64 cols), warp-local over ln ----
#pragma unroll
        for (int i = 0; i < 8; i++) {
            float mx = o[i][0];
#pragma unroll
            for (int j = 1; j < 8; j++) mx = fmaxf(mx, o[i][j]);
            mx = fmaxf(mx, __shfl_xor_sync(0xFFFFFFFFu, mx, 4));
            mx = fmaxf(mx, __shfl_xor_sync(0xFFFFFFFFu, mx, 8));
            mx = fmaxf(mx, __shfl_xor_sync(0xFFFFFFFFu, mx, 16));

            float e[8];
            float s = 0.0f;
#pragma unroll
            for (int j = 0; j < 8; j++) { e[j] = expf(o[i][j] - mx); s += e[j]; }
            s += __shfl_xor_sync(0xFFFFFFFFu, s, 4);
            s += __shfl_xor_sync(0xFFFFFFFFu, s, 8);
            s += __shfl_xor_sync(0xFFFFFFFFu, s, 16);
            float inv = 1.0f / s;

            float* crow = C + (size_t)(m0 + mb + i) * N + n0 + nb;
            *(float4*)(crow)     = make_float4(e[0]*inv, e[1]*inv, e[2]*inv, e[3]*inv);
            *(float4*)(crow + 4) = make_float4(e[4]*inv, e[5]*inv, e[6]*inv, e[7]*inv);
        }
    }
}

// ---------------------------------------------------------------------------
// Output projection GEMM (R16 config, unchanged): cp.async 4-stage, TBM=64.
// ---------------------------------------------------------------------------
#define TBK  16
#define OT_SA   64
#define OT_SBm  192
#define OT_STGA (TBK * OT_SA)          // 1024 floats
#define OT_STGB (TBK * OT_SBm)         // 3072 floats
#define OT_SMEM (4 * (OT_STGA + OT_STGB) * 4)   // 65536 B

__global__ __launch_bounds__(256, 2) void gemm_out(
    const float* __restrict__ AT,      // [256, MQ]
    const float* __restrict__ B,       // [256, 256]
    const float* __restrict__ bias,
    float* __restrict__ C)             // [MQ, 256]
{
    extern __shared__ __align__(16) float smem[];
    float* As = smem;
    float* Bs = smem + 4 * OT_STGA;

    const int tid  = threadIdx.x;
    const int lane = tid & 31;
    const int wid  = tid >> 5;
    const int wm   = wid & 3;
    const int wn   = wid >> 2;
    const int lm   = lane & 3;
    const int ln   = lane >> 2;
    const int m0   = blockIdx.y * 64;
    const int n0   = blockIdx.x * 128;

    const int aofs = wm * 16 + lm * 4;
    const int bofs = (wn * 8 + ln) * 12;
    const int mb   = aofs;
    const int nb   = wn * 64 + ln * 8;

    auto stage = [&](int sg, int kt) {
        const int k0 = kt * TBK;
        {
            int k = tid >> 4, m4 = tid & 15;
            cp16(As + sg * OT_STGA + k * OT_SA + m4 * 4,
                 AT + (size_t)(k0 + k) * MQ + m0 + m4 * 4);
        }
#pragma unroll
        for (int r2 = 0; r2 < 2; r2++) {
            int i = tid + r2 * 256;
            int kk = i >> 5, n4 = i & 31;
            cp16(Bs + sg * OT_STGB + kk * OT_SBm + (n4 >> 1) * 12 + (n4 & 1) * 4,
                 B + (size_t)(k0 + kk) * 256 + n0 + n4 * 4);
        }
    };

    stage(0, 0); CP_COMMIT();
    stage(1, 1); CP_COMMIT();
    stage(2, 2); CP_COMMIT();

    uint64_t acc[4][4];
#pragma unroll
    for (int i = 0; i < 4; i++)
#pragma unroll
        for (int j = 0; j < 4; j++) acc[i][j] = 0ull;

    const int KT = 256 / TBK;   // 16
    int cur = 0;

#pragma unroll 1
    for (int kt = 0; kt < KT; kt++) {
        if (kt <= KT - 3)      { CP_WAIT(2); }
        else if (kt == KT - 2) { CP_WAIT(1); }
        else                   { CP_WAIT(0); }
        __syncthreads();
        if (kt + 3 < KT) {
            stage((kt + 3) & 3, kt + 3);
            CP_COMMIT();
        }

#pragma unroll
        for (int k = 0; k < TBK; k++) {
            float4 a4 = *(const float4*)(As + cur * OT_STGA + k * OT_SA + aofs);
            const uint64_t* bp = (const uint64_t*)(Bs + cur * OT_STGB + k * OT_SBm + bofs);
            uint64_t bd[4];
            bd[0] = bp[0]; bd[1] = bp[1]; bd[2] = bp[2]; bd[3] = bp[3];
            uint64_t ad[4];
            ad[0] = pack2(a4.x, a4.x);
            ad[1] = pack2(a4.y, a4.y);
            ad[2] = pack2(a4.z, a4.z);
            ad[3] = pack2(a4.w, a4.w);
#pragma unroll
            for (int i = 0; i < 4; i++)
#pragma unroll
                for (int j = 0; j < 4; j++)
                    ffma2(acc[i][j], ad[i], bd[j]);
        }

        cur = (cur + 1) & 3;
    }

    float bn[8];
#pragma unroll
    for (int j = 0; j < 8; j++) bn[j] = __ldg(&bias[n0 + nb + j]);

#pragma unroll
    for (int i = 0; i < 4; i++) {
        float o[8];
#pragma unroll
        for (int j = 0; j < 4; j++)
            unpack2(acc[i][j], o[2 * j], o[2 * j + 1]);
#pragma unroll
        for (int j = 0; j < 8; j++) o[j] += bn[j];
        float* crow = C + (size_t)(m0 + mb + i) * 256 + n0 + nb;
        *(float4*)(crow)     = make_float4(o[0], o[1], o[2], o[3]);
        *(float4*)(crow + 4) = make_float4(o[4], o[5], o[6], o[7]);
    }
}

// ---------------------------------------------------------------------------
// Gather: warp per (b,q,h); 8-sample batches; writes g_midT (k-major scatter).
// ---------------------------------------------------------------------------
__global__ __launch_bounds__(256) void gather_kernel(
    const float* __restrict__ v,
    const float4* __restrict__ meta,
    const float* __restrict__ attn,
    float* __restrict__ midT)
{
    const int bq = blockIdx.x;
    const int b = bq >> 10;
    const int h = threadIdx.x >> 5;
    const int lane = threadIdx.x & 31;
    const int corner = lane >> 3;
    const int cg = lane & 7;

    const float4* m4p = meta + ((size_t)(bq * NH + h) * 32) * 4 + corner;
    const float*  ah  = attn + ((size_t)bq * NH + h) * 64;
    const float*  vb  = v + (size_t)b * LEN_V * EMBED + h * HD + cg * 4;

    float4 acc = make_float4(0.f, 0.f, 0.f, 0.f);

#pragma unroll
    for (int base = 0; base < 64; base += 8) {
        float4 aA = __ldg((const float4*)(ah + base));
        float4 aB = __ldg((const float4*)(ah + base + 4));
        float4 m4[4];
#pragma unroll
        for (int q = 0; q < 4; q++)
            m4[q] = __ldg(&m4p[(base / 2 + q) * 4]);

        float4 vv[8];
#pragma unroll
        for (int q = 0; q < 4; q++) {
            vv[2 * q]     = *(const float4*)(vb + __float_as_int(m4[q].x));
            vv[2 * q + 1] = *(const float4*)(vb + __float_as_int(m4[q].z));
        }

        float a8[8] = {aA.x, aA.y, aA.z, aA.w, aB.x, aB.y, aB.z, aB.w};
#pragma unroll
        for (int q = 0; q < 4; q++) {
            float w0 = m4[q].y * a8[2 * q];
            float w1 = m4[q].w * a8[2 * q + 1];
            acc.x = fmaf(w0, vv[2 * q].x, acc.x);
            acc.y = fmaf(w0, vv[2 * q].y, acc.y);
            acc.z = fmaf(w0, vv[2 * q].z, acc.z);
            acc.w = fmaf(w0, vv[2 * q].w, acc.w);
            acc.x = fmaf(w1, vv[2 * q + 1].x, acc.x);
            acc.y = fmaf(w1, vv[2 * q + 1].y, acc.y);
            acc.z = fmaf(w1, vv[2 * q + 1].z, acc.z);
            acc.w = fmaf(w1, vv[2 * q + 1].w, acc.w);
        }
    }

#pragma unroll
    for (int off = 8; off <= 16; off <<= 1) {
        acc.x += __shfl_xor_sync(0xFFFFFFFFu, acc.x, off);
        acc.y += __shfl_xor_sync(0xFFFFFFFFu, acc.y, off);
        acc.z += __shfl_xor_sync(0xFFFFFFFFu, acc.z, off);
        acc.w += __shfl_xor_sync(0xFFFFFFFFu, acc.w, off);
    }

    if (lane < 8) {
        const int ch = h * HD + cg * 4;
        float* col = midT + bq;
        col[(size_t)(ch + 0) * MQ] = acc.x;
        col[(size_t)(ch + 1) * MQ] = acc.y;
        col[(size_t)(ch + 2) * MQ] = acc.z;
        col[(size_t)(ch + 3) * MQ] = acc.w;
    }
}

// ---------------------------------------------------------------------------
// Launch
// ---------------------------------------------------------------------------
extern "C" void kernel_launch(void* const* d_in, const int* in_sizes, int n_in,
                              void* d_out, int out_size)
{
    const float* query  = (const float*)d_in[0];
    const float* refp   = (const float*)d_in[1];
    const float* value  = (const float*)d_in[2];
    const float* W_val  = (const float*)d_in[3];
    const float* b_val  = (const float*)d_in[4];
    const float* W_off  = (const float*)d_in[5];
    const float* b_off  = (const float*)d_in[6];
    const float* W_attn = (const float*)d_in[7];
    const float* b_attn = (const float*)d_in[8];
    const float* W_out  = (const float*)d_in[9];
    const float* b_out  = (const float*)d_in[10];

    float* out  = (float*)d_out;
    float* loc  = out + LOC_OFFSET;
    float* attn = out + ATTN_OFFSET;

    float* gv;
    float* gmidT;
    float4* gmeta;
    float* gvT;
    float* gqT;
    cudaGetSymbolAddress((void**)&gv, g_v);
    cudaGetSymbolAddress((void**)&gmidT, g_midT);
    cudaGetSymbolAddress((void**)&gmeta, g_meta);
    cudaGetSymbolAddress((void**)&gvT, g_vT);
    cudaGetSymbolAddress((void**)&gqT, g_qT);

    cudaFuncSetAttribute(mega_gemm,
                         cudaFuncAttributeMaxDynamicSharedMemorySize, MEGA_SMEM);
    cudaFuncSetAttribute(gemm_out,
                         cudaFuncAttributeMaxDynamicSharedMemorySize, OT_SMEM);

    // 0. one-shot transpose of value + query (k-major A operands)
    transpose_kernel<<<VT_TILES + QT_TILES, 256>>>(value, query, gvT, gqT);

    // 1. all three front GEMMs in one launch (724 CTAs, TBK=32, 2-buffer)
    mega_gemm<<<MEGA_CTAS, 256, MEGA_SMEM>>>(gvT, gqT, W_val, b_val, W_off, b_off,
                                             W_attn, b_attn, refp, gv, loc, attn, gmeta);

    // 2. batched branchless gather -> g_midT (transposed)
    gather_kernel<<<BS * LQ, 256>>>(gv, gmeta, attn, gmidT);

    // 3. output projection (128 CTAs, 4-stage cp.async, TBM=64)
    {
        dim3 grid(EMBED / 128, MQ / 64);
        gemm_out<<<grid, 256, OT_SMEM>>>(gmidT, W_out, b_out, out);
    }
}